// round 1
// baseline (speedup 1.0000x reference)
#include <cuda_runtime.h>

// SSIM loss, fused separable 11x11 Gaussian pipeline.
// Trick: with u = x+y, v = x-y we only need 4 conv fields:
//   E[u], E[v], E[u^2], E[v^2]
//   mu1*mu2        = (E[u]^2 - E[v]^2)/4
//   mu1^2 + mu2^2  = (E[u]^2 + E[v]^2)/2
//   E[xy]          = (E[u^2] - E[v^2])/4   -> sigma12 = E[xy] - mu1*mu2
//   E[x^2+y^2]     = (E[u^2] + E[v^2])/2   -> s1+s2   = that - (mu1^2+mu2^2)

#define IMG       512
#define NIMG      96            // 32 batch * 3 channels
#define TX        32            // output tile width
#define TY        64            // output tile height
#define HALO      5
#define IN_W      42            // TX + 2*HALO
#define IN_H      74            // TY + 2*HALO
#define IN_STRIDE 48            // padded row stride (floats) for su/sv
#define TILES_X   16
#define TILES_Y   8
#define NBLOCKS   (TILES_X * TILES_Y * NIMG)   // 12288
#define NPIX_D    25165824.0    // 32*3*512*512

// Normalized 1D Gaussian, sigma=1.5, 11 taps (compile-time constants -> FFMA-imm)
__device__ __constant__ static const float kDummy = 0.f; // (keep TU non-empty for constexpr use)

#define W0 0.26601172f
#define W1 0.21300575f
#define W2 0.10936060f
#define W3 0.03600077f
#define W4 0.00759876f
#define W5 0.00102838f

__device__ float g_partials[NBLOCKS];

__global__ __launch_bounds__(256) void ssim_tile_kernel(
    const float* __restrict__ clean,
    const float* __restrict__ adv)
{
    extern __shared__ float smem[];
    // layout (floats):
    float* su  = smem;                          // IN_H * IN_STRIDE = 3552
    float* sv  = su  + IN_H * IN_STRIDE;        // 3552
    float* hu  = sv  + IN_H * IN_STRIDE;        // IN_H * TX = 2368
    float* hv  = hu  + IN_H * TX;
    float* huu = hv  + IN_H * TX;
    float* hvv = huu + IN_H * TX;
    __shared__ float wsum[8];

    const float W[11] = {W5, W4, W3, W2, W1, W0, W1, W2, W3, W4, W5};

    const int tid = threadIdx.x;
    const int x0 = blockIdx.x * TX - HALO;
    const int y0 = blockIdx.y * TY - HALO;
    const float* __restrict__ cbase = clean + (size_t)blockIdx.z * (IMG * IMG);
    const float* __restrict__ abase = adv   + (size_t)blockIdx.z * (IMG * IMG);

    // ---- Phase 1: load halo'd tile, build u = x+y, v = x-y ----
    for (int i = tid; i < IN_H * IN_W; i += 256) {
        int r = i / IN_W;
        int c = i - r * IN_W;
        int gx = x0 + c;
        int gy = y0 + r;
        float x = 0.f, y = 0.f;
        if (gx >= 0 && gx < IMG && gy >= 0 && gy < IMG) {
            int gidx = gy * IMG + gx;
            x = __ldg(cbase + gidx);
            y = __ldg(abase + gidx);
        }
        su[r * IN_STRIDE + c] = x + y;
        sv[r * IN_STRIDE + c] = x - y;
    }
    __syncthreads();

    // ---- Phase 2: horizontal conv. 4 output cols per thread (float4 LDS, conflict-free).
    // Groups: IN_H rows * 8 col-groups = 592; 256 threads -> <=3 iters.
    #pragma unroll 1
    for (int gi = tid; gi < IN_H * 8; gi += 256) {
        int r  = gi >> 3;
        int cb = (gi & 7) << 2;   // 0,4,...,28
        const float* surow = su + r * IN_STRIDE;
        const float* svrow = sv + r * IN_STRIDE;

        float uu[16], vv[16];
        *(float4*)&uu[0]  = *(const float4*)(surow + cb);
        *(float4*)&uu[4]  = *(const float4*)(surow + cb + 4);
        *(float4*)&uu[8]  = *(const float4*)(surow + cb + 8);
        *(float4*)&uu[12] = *(const float4*)(surow + cb + 12);
        *(float4*)&vv[0]  = *(const float4*)(svrow + cb);
        *(float4*)&vv[4]  = *(const float4*)(svrow + cb + 4);
        *(float4*)&vv[8]  = *(const float4*)(svrow + cb + 8);
        *(float4*)&vv[12] = *(const float4*)(svrow + cb + 12);

        float acu[4]  = {0.f, 0.f, 0.f, 0.f};
        float acv[4]  = {0.f, 0.f, 0.f, 0.f};
        float acuu[4] = {0.f, 0.f, 0.f, 0.f};
        float acvv[4] = {0.f, 0.f, 0.f, 0.f};

        #pragma unroll
        for (int c = 0; c < 14; c++) {
            float U = uu[c], V = vv[c];
            float U2 = U * U;
            float V2 = V * V;
            #pragma unroll
            for (int j = 0; j < 4; j++) {
                int k = c - j;
                if (k >= 0 && k < 11) {
                    float w = W[k];           // compile-time constant -> FFMA imm
                    acu[j]  += w * U;
                    acv[j]  += w * V;
                    acuu[j] += w * U2;
                    acvv[j] += w * V2;
                }
            }
        }
        int ho = r * TX + cb;
        *(float4*)(hu  + ho) = make_float4(acu[0],  acu[1],  acu[2],  acu[3]);
        *(float4*)(hv  + ho) = make_float4(acv[0],  acv[1],  acv[2],  acv[3]);
        *(float4*)(huu + ho) = make_float4(acuu[0], acuu[1], acuu[2], acuu[3]);
        *(float4*)(hvv + ho) = make_float4(acvv[0], acvv[1], acvv[2], acvv[3]);
    }
    __syncthreads();

    // ---- Phase 3: vertical conv, 8 output rows per thread + SSIM epilogue ----
    const int tx  = tid & 31;
    const int tyi = tid >> 5;      // 0..7
    const int rb  = tyi * 8;       // output row base within tile

    float au[8]  = {0,0,0,0,0,0,0,0};
    float av[8]  = {0,0,0,0,0,0,0,0};
    float auu[8] = {0,0,0,0,0,0,0,0};
    float avv[8] = {0,0,0,0,0,0,0,0};

    #pragma unroll
    for (int rr = 0; rr < 18; rr++) {
        int r = rb + rr;
        float U  = hu [r * TX + tx];
        float V  = hv [r * TX + tx];
        float U2 = huu[r * TX + tx];
        float V2 = hvv[r * TX + tx];
        #pragma unroll
        for (int j = 0; j < 8; j++) {
            int k = rr - j;
            if (k >= 0 && k < 11) {
                float w = W[k];
                au[j]  += w * U;
                av[j]  += w * V;
                auu[j] += w * U2;
                avv[j] += w * V2;
            }
        }
    }

    const float C1 = 1e-4f;       // 0.01^2
    const float C2 = 9e-4f;       // 0.03^2
    float lsum = 0.f;
    #pragma unroll
    for (int j = 0; j < 8; j++) {
        float ms2  = au[j] * au[j];
        float md2  = av[j] * av[j];
        float mu12 = 0.25f * (ms2 - md2);      // mu1*mu2
        float musq = 0.5f  * (ms2 + md2);      // mu1^2 + mu2^2
        float exy  = 0.25f * (auu[j] - avv[j]);
        float es   = 0.5f  * (auu[j] + avv[j]);
        float s12  = exy - mu12;               // sigma12
        float ssum = es  - musq;               // sigma1^2 + sigma2^2
        float num  = (2.f * mu12 + C1) * (2.f * s12 + C2);
        float den  = (musq + C1) * (ssum + C2);
        lsum += __fdividef(num, den);
    }

    // ---- block reduce -> per-block partial (deterministic, no atomics) ----
    #pragma unroll
    for (int o = 16; o; o >>= 1)
        lsum += __shfl_xor_sync(0xFFFFFFFFu, lsum, o);
    if (tx == 0) wsum[tyi] = lsum;
    __syncthreads();
    if (tid == 0) {
        float s = 0.f;
        #pragma unroll
        for (int i = 0; i < 8; i++) s += wsum[i];
        int bid = (blockIdx.z * TILES_Y + blockIdx.y) * TILES_X + blockIdx.x;
        g_partials[bid] = s;
    }
}

__global__ void ssim_finalize_kernel(float* __restrict__ out)
{
    __shared__ double sm[256];
    double s = 0.0;
    for (int i = threadIdx.x; i < NBLOCKS; i += 256)
        s += (double)g_partials[i];
    sm[threadIdx.x] = s;
    __syncthreads();
    #pragma unroll
    for (int o = 128; o; o >>= 1) {
        if (threadIdx.x < o) sm[threadIdx.x] += sm[threadIdx.x + o];
        __syncthreads();
    }
    if (threadIdx.x == 0)
        out[0] = (float)(1.0 - sm[0] / NPIX_D);
}

extern "C" void kernel_launch(void* const* d_in, const int* in_sizes, int n_in,
                              void* d_out, int out_size)
{
    (void)in_sizes; (void)n_in; (void)out_size; (void)kDummy;
    const float* clean = (const float*)d_in[0];
    const float* adv   = (const float*)d_in[1];

    const int smem_bytes = (2 * IN_H * IN_STRIDE + 4 * IN_H * TX) * (int)sizeof(float); // 66304
    cudaFuncSetAttribute(ssim_tile_kernel,
                         cudaFuncAttributeMaxDynamicSharedMemorySize, smem_bytes);

    dim3 grid(TILES_X, TILES_Y, NIMG);
    ssim_tile_kernel<<<grid, 256, smem_bytes>>>(clean, adv);
    ssim_finalize_kernel<<<1, 256>>>((float*)d_out);
}

// round 3
// speedup vs baseline: 1.0253x; 1.0253x over previous
#include <cuda_runtime.h>

// SSIM loss, fused separable 11x11 Gaussian pipeline.
// u = x+y, v = x-y -> only 4 conv fields needed: E[u], E[v], E[u^2], E[v^2].

#define IMG       512
#define NIMG      96            // 32 batch * 3 channels
#define TX        32            // output tile width
#define TY        64            // output tile height
#define HALO      5
#define IN_W      42            // TX + 2*HALO
#define IN_H      74            // TY + 2*HALO
#define IN_STRIDE 44            // padded row stride (floats) for su/sv
#define TILES_X   16
#define TILES_Y   8
#define NBLOCKS   (TILES_X * TILES_Y * NIMG)   // 12288
#define NPIX_D    25165824.0    // 32*3*512*512

// Normalized 1D Gaussian, sigma=1.5, 11 taps. __device__ constexpr ->
// visible in device code AND folded to FFMA immediates (all indices are
// compile-time constants after full unroll).
__device__ constexpr float KW[11] = {
    0.00102838f, 0.00759876f, 0.03600077f, 0.10936060f, 0.21300575f,
    0.26601172f,
    0.21300575f, 0.10936060f, 0.03600077f, 0.00759876f, 0.00102838f
};

__device__ float g_partials[NBLOCKS];

__global__ __launch_bounds__(256, 3) void ssim_tile_kernel(
    const float* __restrict__ clean,
    const float* __restrict__ adv)
{
    extern __shared__ float smem[];
    // layout (floats):
    float* su  = smem;                          // IN_H * IN_STRIDE = 3256
    float* sv  = su  + IN_H * IN_STRIDE;        // 3256
    float* hu  = sv  + IN_H * IN_STRIDE;        // IN_H * TX = 2368
    float* hv  = hu  + IN_H * TX;
    float* huu = hv  + IN_H * TX;
    float* hvv = huu + IN_H * TX;
    __shared__ float wsum[8];

    const int tid = threadIdx.x;
    const int x0 = blockIdx.x * TX - HALO;
    const int y0 = blockIdx.y * TY - HALO;
    const float* __restrict__ cbase = clean + (size_t)blockIdx.z * (IMG * IMG);
    const float* __restrict__ abase = adv   + (size_t)blockIdx.z * (IMG * IMG);

    // ---- Phase 1: load halo'd tile, build u = x+y, v = x-y ----
    #pragma unroll 1
    for (int i = tid; i < IN_H * IN_W; i += 256) {
        int r = i / IN_W;
        int c = i - r * IN_W;
        int gx = x0 + c;
        int gy = y0 + r;
        float x = 0.f, y = 0.f;
        if (gx >= 0 && gx < IMG && gy >= 0 && gy < IMG) {
            int gidx = gy * IMG + gx;
            x = __ldg(cbase + gidx);
            y = __ldg(abase + gidx);
        }
        su[r * IN_STRIDE + c] = x + y;
        sv[r * IN_STRIDE + c] = x - y;
    }
    __syncthreads();

    // ---- Phase 2: horizontal conv. 4 output cols per thread (float4 LDS). ----
    #pragma unroll 1
    for (int gi = tid; gi < IN_H * 8; gi += 256) {
        int r  = gi >> 3;
        int cb = (gi & 7) << 2;   // 0,4,...,28
        const float* surow = su + r * IN_STRIDE;
        const float* svrow = sv + r * IN_STRIDE;

        float uu[16], vv[16];
        *(float4*)&uu[0]  = *(const float4*)(surow + cb);
        *(float4*)&uu[4]  = *(const float4*)(surow + cb + 4);
        *(float4*)&uu[8]  = *(const float4*)(surow + cb + 8);
        *(float4*)&uu[12] = *(const float4*)(surow + cb + 12);
        *(float4*)&vv[0]  = *(const float4*)(svrow + cb);
        *(float4*)&vv[4]  = *(const float4*)(svrow + cb + 4);
        *(float4*)&vv[8]  = *(const float4*)(svrow + cb + 8);
        *(float4*)&vv[12] = *(const float4*)(svrow + cb + 12);

        float acu[4]  = {0.f, 0.f, 0.f, 0.f};
        float acv[4]  = {0.f, 0.f, 0.f, 0.f};
        float acuu[4] = {0.f, 0.f, 0.f, 0.f};
        float acvv[4] = {0.f, 0.f, 0.f, 0.f};

        #pragma unroll
        for (int c = 0; c < 14; c++) {
            float U = uu[c], V = vv[c];
            float U2 = U * U;
            float V2 = V * V;
            #pragma unroll
            for (int j = 0; j < 4; j++) {
                int k = c - j;
                if (k >= 0 && k < 11) {
                    acu[j]  += KW[k] * U;
                    acv[j]  += KW[k] * V;
                    acuu[j] += KW[k] * U2;
                    acvv[j] += KW[k] * V2;
                }
            }
        }
        int ho = r * TX + cb;
        *(float4*)(hu  + ho) = make_float4(acu[0],  acu[1],  acu[2],  acu[3]);
        *(float4*)(hv  + ho) = make_float4(acv[0],  acv[1],  acv[2],  acv[3]);
        *(float4*)(huu + ho) = make_float4(acuu[0], acuu[1], acuu[2], acuu[3]);
        *(float4*)(hvv + ho) = make_float4(acvv[0], acvv[1], acvv[2], acvv[3]);
    }
    __syncthreads();

    // ---- Phase 3: vertical conv, 8 output rows per thread + SSIM epilogue ----
    const int tx  = tid & 31;
    const int tyi = tid >> 5;      // 0..7
    const int rb  = tyi * 8;       // output row base within tile

    float au[8]  = {0,0,0,0,0,0,0,0};
    float av[8]  = {0,0,0,0,0,0,0,0};
    float auu[8] = {0,0,0,0,0,0,0,0};
    float avv[8] = {0,0,0,0,0,0,0,0};

    #pragma unroll
    for (int rr = 0; rr < 18; rr++) {
        int r = rb + rr;
        float U  = hu [r * TX + tx];
        float V  = hv [r * TX + tx];
        float U2 = huu[r * TX + tx];
        float V2 = hvv[r * TX + tx];
        #pragma unroll
        for (int j = 0; j < 8; j++) {
            int k = rr - j;
            if (k >= 0 && k < 11) {
                au[j]  += KW[k] * U;
                av[j]  += KW[k] * V;
                auu[j] += KW[k] * U2;
                avv[j] += KW[k] * V2;
            }
        }
    }

    const float C1 = 1e-4f;       // 0.01^2
    const float C2 = 9e-4f;       // 0.03^2
    float lsum = 0.f;
    #pragma unroll
    for (int j = 0; j < 8; j++) {
        float ms2  = au[j] * au[j];
        float md2  = av[j] * av[j];
        float mu12 = 0.25f * (ms2 - md2);      // mu1*mu2
        float musq = 0.5f  * (ms2 + md2);      // mu1^2 + mu2^2
        float exy  = 0.25f * (auu[j] - avv[j]);
        float es   = 0.5f  * (auu[j] + avv[j]);
        float s12  = exy - mu12;               // sigma12
        float ssum = es  - musq;               // sigma1^2 + sigma2^2
        float num  = (2.f * mu12 + C1) * (2.f * s12 + C2);
        float den  = (musq + C1) * (ssum + C2);
        lsum += __fdividef(num, den);
    }

    // ---- block reduce -> per-block partial (deterministic, no atomics) ----
    #pragma unroll
    for (int o = 16; o; o >>= 1)
        lsum += __shfl_xor_sync(0xFFFFFFFFu, lsum, o);
    if (tx == 0) wsum[tyi] = lsum;
    __syncthreads();
    if (tid == 0) {
        float s = 0.f;
        #pragma unroll
        for (int i = 0; i < 8; i++) s += wsum[i];
        int bid = (blockIdx.z * TILES_Y + blockIdx.y) * TILES_X + blockIdx.x;
        g_partials[bid] = s;
    }
}

__global__ __launch_bounds__(256) void ssim_finalize_kernel(float* __restrict__ out)
{
    __shared__ double sm[256];
    // 12288 floats = 3072 float4; 256 threads -> 12 independent float4 each (MLP=12)
    const float4* p4 = (const float4*)g_partials;
    double s = 0.0;
    #pragma unroll
    for (int it = 0; it < 12; it++) {
        float4 v = p4[it * 256 + threadIdx.x];
        s += (double)((v.x + v.y) + (v.z + v.w));
    }
    sm[threadIdx.x] = s;
    __syncthreads();
    #pragma unroll
    for (int o = 128; o; o >>= 1) {
        if (threadIdx.x < o) sm[threadIdx.x] += sm[threadIdx.x + o];
        __syncthreads();
    }
    if (threadIdx.x == 0)
        out[0] = (float)(1.0 - sm[0] / NPIX_D);
}

// No-op kernels: pad the launch count to 5 per kernel_launch call so that
// ncu's fixed "-s 5 -c 1" (skip 5, capture 1) lands on ssim_tile_kernel
// (launch index 6 == 1 mod 5). Remove once profiling data is in hand.
__global__ void ssim_noop_kernel() {}

extern "C" void kernel_launch(void* const* d_in, const int* in_sizes, int n_in,
                              void* d_out, int out_size)
{
    (void)in_sizes; (void)n_in; (void)out_size;
    const float* clean = (const float*)d_in[0];
    const float* adv   = (const float*)d_in[1];

    const int smem_bytes = (2 * IN_H * IN_STRIDE + 4 * IN_H * TX) * (int)sizeof(float); // 63936
    cudaFuncSetAttribute(ssim_tile_kernel,
                         cudaFuncAttributeMaxDynamicSharedMemorySize, smem_bytes);

    dim3 grid(TILES_X, TILES_Y, NIMG);
    ssim_tile_kernel<<<grid, 256, smem_bytes>>>(clean, adv);
    ssim_finalize_kernel<<<1, 256>>>((float*)d_out);
    ssim_noop_kernel<<<1, 32>>>();
    ssim_noop_kernel<<<1, 32>>>();
    ssim_noop_kernel<<<1, 32>>>();
}